// round 15
// baseline (speedup 1.0000x reference)
#include <cuda_runtime.h>
#include <cuda_bf16.h>
#include <mma.h>
#include <cstdint>

using namespace nvcuda;
typedef unsigned long long ull;

#define T_TOK 4096
#define DIM   1024
#define HID   2048
#define NEXP  8
#define NP    (T_TOK * 2)
#define BM    128
#define MAXTILES (NP / BM + NEXP)   // 72

// ---------------- scratch (112 MB total) -------------------------------------
__device__ int   g_pair[NP];
__device__ int   g_pos[NP];
__device__ float g_gate[NP];
__device__ int   g_expert[NP];
__device__ int   g_counts[NEXP];
__device__ int   g_fill[NEXP];
__device__ int   g_offs[NEXP + 1];
__device__ int   g_tile_e[MAXTILES];
__device__ int   g_tile_r0[MAXTILES];
__device__ int   g_tile_rows[MAXTILES];
__device__ int   g_ntiles;
__device__ float g_P[(size_t)NP * DIM];               // 32 MB
__device__ __nv_bfloat16 g_Hh[(size_t)NP * HID];      // 32 MB
__device__ __nv_bfloat16 g_Hl[(size_t)NP * HID];      // 32 MB
__device__ __nv_bfloat16 g_Xh[(size_t)T_TOK * DIM];   // 8 MB
__device__ __nv_bfloat16 g_Xl[(size_t)T_TOK * DIM];   // 8 MB

// ---------------- truncation split (PRMT prefix) -----------------------------
__device__ __forceinline__ void split4t(float4 v, ull& hp, ull& lp) {
    uint32_t bx = __float_as_uint(v.x), by = __float_as_uint(v.y),
             bz = __float_as_uint(v.z), bw = __float_as_uint(v.w);
    uint32_t h01 = __byte_perm(bx, by, 0x7632);
    uint32_t h23 = __byte_perm(bz, bw, 0x7632);
    float rx = v.x - __uint_as_float(bx & 0xFFFF0000u);
    float ry = v.y - __uint_as_float(by & 0xFFFF0000u);
    float rz = v.z - __uint_as_float(bz & 0xFFFF0000u);
    float rw = v.w - __uint_as_float(bw & 0xFFFF0000u);
    uint32_t l01 = __byte_perm(__float_as_uint(rx), __float_as_uint(ry), 0x7632);
    uint32_t l23 = __byte_perm(__float_as_uint(rz), __float_as_uint(rw), 0x7632);
    hp = (ull)h01 | ((ull)h23 << 32);
    lp = (ull)l01 | ((ull)l23 << 32);
}

// ---------------- routing path (verbatim, proven) -----------------------------
__global__ void init_kernel() {
    int t = threadIdx.x;
    if (t < NEXP) { g_counts[t] = 0; g_fill[t] = 0; }
}

__global__ void router_kernel(const float* __restrict__ x,
                              const float* __restrict__ Wr) {
    int warp = (blockIdx.x * blockDim.x + threadIdx.x) >> 5;
    int lane = threadIdx.x & 31;
    if (warp >= T_TOK) return;
    const float* xr = x + (size_t)warp * DIM;
    float acc[NEXP];
#pragma unroll
    for (int e = 0; e < NEXP; e++) acc[e] = 0.f;
    for (int d = lane; d < DIM; d += 32) {
        float xv = xr[d];
        const float4* w = reinterpret_cast<const float4*>(Wr + (size_t)d * NEXP);
        float4 w0 = w[0], w1 = w[1];
        acc[0] = fmaf(xv, w0.x, acc[0]); acc[1] = fmaf(xv, w0.y, acc[1]);
        acc[2] = fmaf(xv, w0.z, acc[2]); acc[3] = fmaf(xv, w0.w, acc[3]);
        acc[4] = fmaf(xv, w1.x, acc[4]); acc[5] = fmaf(xv, w1.y, acc[5]);
        acc[6] = fmaf(xv, w1.z, acc[6]); acc[7] = fmaf(xv, w1.w, acc[7]);
    }
#pragma unroll
    for (int off = 16; off > 0; off >>= 1)
#pragma unroll
        for (int e = 0; e < NEXP; e++)
            acc[e] += __shfl_down_sync(0xffffffffu, acc[e], off);
    if (lane == 0) {
        int i0 = 0; float m0 = acc[0];
#pragma unroll
        for (int e = 1; e < NEXP; e++)
            if (acc[e] > m0) { m0 = acc[e]; i0 = e; }
        int i1 = -1; float m1 = -3.4e38f;
#pragma unroll
        for (int e = 0; e < NEXP; e++)
            if (e != i0 && acc[e] > m1) { m1 = acc[e]; i1 = e; }
        float g0 = 1.f / (1.f + expf(m1 - m0));
        int p0 = warp * 2, p1 = p0 + 1;
        g_expert[p0] = i0; g_gate[p0] = g0;
        g_expert[p1] = i1; g_gate[p1] = 1.f - g0;
        atomicAdd(&g_counts[i0], 1);
        atomicAdd(&g_counts[i1], 1);
    }
}

__global__ void scan_kernel() {
    int off = 0;
    for (int e = 0; e < NEXP; e++) { g_offs[e] = off; off += g_counts[e]; }
    g_offs[NEXP] = off;
    int nt = 0;
    for (int e = 0; e < NEXP; e++) {
        int c = g_counts[e], base = g_offs[e];
        for (int r = 0; r < c; r += BM) {
            g_tile_e[nt] = e; g_tile_r0[nt] = base + r;
            g_tile_rows[nt] = (c - r < BM) ? (c - r) : BM;
            nt++;
        }
    }
    g_ntiles = nt;
}

__global__ void scatter_kernel() {
    int p = blockIdx.x * blockDim.x + threadIdx.x;
    if (p >= NP) return;
    int e = g_expert[p];
    int row = g_offs[e] + atomicAdd(&g_fill[e], 1);
    g_pair[row] = p;
    g_pos[p] = row;
}

__global__ void x_split_kernel(const float* __restrict__ x) {
    size_t i = ((size_t)blockIdx.x * 256 + threadIdx.x) * 4;
    float4 v = *reinterpret_cast<const float4*>(x + i);
    ull hp, lp; split4t(v, hp, lp);
    *reinterpret_cast<ull*>(&g_Xh[i]) = hp;
    *reinterpret_cast<ull*>(&g_Xl[i]) = lp;
}

// ---------------- GEMM1: tensor-split warps (4m x 2tensor), 64 acc regs ------
// smem (bf16 elems): Ah[128*40]@0 | Al@5120 | B1h[32*72]@10240 | B1l@12544 |
//   B3h@14848 | B3l@17152  -> 38912 B. Epilogue stages 2x[64][72] f32 = 36864 B.
#define G1_SMEM 38912

__global__ __launch_bounds__(256, 2)
void gemm1_wmma(const float* __restrict__ W1,
                const float* __restrict__ W3) {
    if ((int)blockIdx.x >= g_ntiles) return;
    __shared__ __align__(16) char sm[G1_SMEM];
    __shared__ int s_tok[128];
    __nv_bfloat16* Ah  = (__nv_bfloat16*)sm;
    __nv_bfloat16* Al  = Ah + 5120;
    __nv_bfloat16* B1h = Ah + 10240;
    __nv_bfloat16* B1l = Ah + 12544;
    __nv_bfloat16* B3h = Ah + 14848;
    __nv_bfloat16* B3l = Ah + 17152;

    int e    = g_tile_e[blockIdx.x];
    int row0 = g_tile_r0[blockIdx.x];
    int rows = g_tile_rows[blockIdx.x];
    int n0   = blockIdx.y * 64;
    int tid  = threadIdx.x, wid = tid >> 5;
    int wm = wid & 3, wt = wid >> 2;   // wt: 0 -> W1 accumulators, 1 -> W3

    if (tid < 128) s_tok[tid] = (tid < rows) ? (g_pair[row0 + tid] >> 1) : -1;
    __syncthreads();

    const float* W1e = W1 + (size_t)e * DIM * HID;
    const float* W3e = W3 + (size_t)e * DIM * HID;

    // each warp: 8 acc frags (64 regs) covering 32 rows x 64 cols of ONE tensor
    wmma::fragment<wmma::accumulator, 16, 16, 16, float> acc[2][4];
#pragma unroll
    for (int i = 0; i < 2; i++)
#pragma unroll
        for (int j = 0; j < 4; j++) wmma::fill_fragment(acc[i][j], 0.f);

    __nv_bfloat16* myBh = wt ? B3h : B1h;
    __nv_bfloat16* myBl = wt ? B3l : B1l;

    for (int ch = 0; ch < DIM / 32; ch++) {
        int k0 = ch * 32;
        // A fill: pre-split bf16 gathered copies
#pragma unroll
        for (int p = 0; p < 4; p++) {
            int li = p * 256 + tid;
            int hl = li >> 9, r = (li >> 2) & 127, q = li & 3;
            int tok = s_tok[r];
            uint4 v = make_uint4(0u, 0u, 0u, 0u);
            const __nv_bfloat16* src = hl ? g_Xl : g_Xh;
            if (tok >= 0)
                v = *reinterpret_cast<const uint4*>(src + (size_t)tok * DIM + k0 + q * 8);
            *reinterpret_cast<uint4*>((hl ? Al : Ah) + r * 40 + q * 8) = v;
        }
        // B fill: W1 and W3 fp32 [32 k-rows][64 n-cols], trunc-split.
#pragma unroll
        for (int p = 0; p < 4; p++) {
            int li = p * 256 + tid;
            int t = li >> 9, rr = li & 511, r = rr >> 4, q = rr & 15;
            const float* src = t ? W3e : W1e;
            float4 v = *reinterpret_cast<const float4*>(
                src + (size_t)(k0 + r) * HID + n0 + q * 4);
            ull hp, lp; split4t(v, hp, lp);
            __nv_bfloat16* dh = t ? B3h : B1h;
            __nv_bfloat16* dl = t ? B3l : B1l;
            *reinterpret_cast<ull*>(dh + r * 72 + q * 4) = hp;
            *reinterpret_cast<ull*>(dl + r * 72 + q * 4) = lp;
        }
        __syncthreads();

#pragma unroll
        for (int ks = 0; ks < 2; ks++) {
            wmma::fragment<wmma::matrix_a, 16, 16, 16, __nv_bfloat16, wmma::row_major> ah[2], al[2];
#pragma unroll
            for (int i = 0; i < 2; i++) {
                wmma::load_matrix_sync(ah[i], Ah + (wm * 32 + i * 16) * 40 + ks * 16, 40);
                wmma::load_matrix_sync(al[i], Al + (wm * 32 + i * 16) * 40 + ks * 16, 40);
            }
#pragma unroll
            for (int j = 0; j < 4; j++) {
                int bcol = j * 16;
                wmma::fragment<wmma::matrix_b, 16, 16, 16, __nv_bfloat16, wmma::row_major> bf;
                wmma::load_matrix_sync(bf, myBh + ks * 16 * 72 + bcol, 72);
#pragma unroll
                for (int i = 0; i < 2; i++) {
                    wmma::mma_sync(acc[i][j], ah[i], bf, acc[i][j]);
                    wmma::mma_sync(acc[i][j], al[i], bf, acc[i][j]);
                }
                wmma::load_matrix_sync(bf, myBl + ks * 16 * 72 + bcol, 72);
#pragma unroll
                for (int i = 0; i < 2; i++)
                    wmma::mma_sync(acc[i][j], ah[i], bf, acc[i][j]);
            }
        }
        __syncthreads();
    }

    // epilogue: two m-half passes. z1 (wt=0) -> stageA, z3 (wt=1) -> stageB,
    // then 256 threads compute silu(z1)*z3 and split-write to g_H.
    float* stageA = (float*)sm;                 // [64][72]
    float* stageB = stageA + 64 * 72;           // [64][72]
#pragma unroll
    for (int half = 0; half < 2; half++) {
        if ((wm >> 1) == half) {
            float* dst = wt ? stageB : stageA;
            int rbase = (wm & 1) * 32;
#pragma unroll
            for (int i = 0; i < 2; i++)
#pragma unroll
                for (int j = 0; j < 4; j++)
                    wmma::store_matrix_sync(dst + (rbase + i * 16) * 72 + j * 16,
                                            acc[i][j], 72, wmma::mem_row_major);
        }
        __syncthreads();
#pragma unroll
        for (int p = 0; p < 4; p++) {
            int li = p * 256 + tid;
            int r = li >> 4, q = li & 15;          // r 0..63, q 0..15 (col q*4)
            int grow = half * 64 + r;
            if (grow < rows) {
                const float* z1p = stageA + r * 72 + q * 4;
                const float* z3p = stageB + r * 72 + q * 4;
                float4 o;
                float z;
                z = z1p[0]; o.x = z / (1.f + __expf(-z)) * z3p[0];
                z = z1p[1]; o.y = z / (1.f + __expf(-z)) * z3p[1];
                z = z1p[2]; o.z = z / (1.f + __expf(-z)) * z3p[2];
                z = z1p[3]; o.w = z / (1.f + __expf(-z)) * z3p[3];
                ull hp, lp; split4t(o, hp, lp);
                size_t ob = (size_t)(row0 + grow) * HID + n0 + q * 4;
                *reinterpret_cast<ull*>(&g_Hh[ob]) = hp;
                *reinterpret_cast<ull*>(&g_Hl[ob]) = lp;
            }
        }
        __syncthreads();
    }
}

// ---------------- GEMM2: P = h @ W2, 128x128 tiles, 2 CTA/SM (R12 verbatim) ---
#define G2_SMEM 37888

__global__ __launch_bounds__(256, 2)
void gemm2_wmma(const float* __restrict__ W2) {
    if ((int)blockIdx.x >= g_ntiles) return;
    __shared__ __align__(16) char sm[G2_SMEM];
    __nv_bfloat16* Ah = (__nv_bfloat16*)sm;
    __nv_bfloat16* Al = Ah + 5120;
    __nv_bfloat16* Bh = Ah + 10240;
    __nv_bfloat16* Bl = Ah + 14592;
    float* stage = (float*)sm;

    int e    = g_tile_e[blockIdx.x];
    int row0 = g_tile_r0[blockIdx.x];
    int rows = g_tile_rows[blockIdx.x];
    int n0   = blockIdx.y * 128;
    int tid  = threadIdx.x, wid = tid >> 5;
    int wm = wid & 3, wn = wid >> 2;

    const float* W2e = W2 + (size_t)e * HID * DIM;

    wmma::fragment<wmma::accumulator, 16, 16, 16, float> acc[2][4];
#pragma unroll
    for (int i = 0; i < 2; i++)
#pragma unroll
        for (int j = 0; j < 4; j++) wmma::fill_fragment(acc[i][j], 0.f);

    for (int ch = 0; ch < HID / 32; ch++) {
        int k0 = ch * 32;
#pragma unroll
        for (int p = 0; p < 2; p++) {
            int li = p * 256 + tid;
            int r = li >> 2, q = li & 3;
            uint4 vh = make_uint4(0u, 0u, 0u, 0u), vl = vh;
            if (r < rows) {
                size_t s = (size_t)(row0 + r) * HID + k0 + q * 8;
                vh = *reinterpret_cast<const uint4*>(&g_Hh[s]);
                vl = *reinterpret_cast<const uint4*>(&g_Hl[s]);
            }
            *reinterpret_cast<uint4*>(Ah + r * 40 + q * 8) = vh;
            *reinterpret_cast<uint4*>(Al + r * 40 + q * 8) = vl;
        }
#pragma unroll
        for (int p = 0; p < 4; p++) {
            int li = p * 256 + tid;
            int r = li >> 5, q = li & 31;
            float4 v = *reinterpret_cast<const float4*>(
                W2e + (size_t)(k0 + r) * DIM + n0 + q * 4);
            ull hp, lp; split4t(v, hp, lp);
            *reinterpret_cast<ull*>(Bh + r * 136 + q * 4) = hp;
            *reinterpret_cast<ull*>(Bl + r * 136 + q * 4) = lp;
        }
        __syncthreads();

#pragma unroll
        for (int ks = 0; ks < 2; ks++) {
            wmma::fragment<wmma::matrix_a, 16, 16, 16, __nv_bfloat16, wmma::row_major> ah[2], al[2];
#pragma unroll
            for (int i = 0; i < 2; i++) {
                wmma::load_matrix_sync(ah[i], Ah + (wm * 32 + i * 16) * 40 + ks * 16, 40);
                wmma::load_matrix_sync(al[i], Al + (wm * 32 + i * 16) * 40 + ks * 16, 40);
            }
#pragma unroll
            for (int j = 0; j < 4; j++) {
                int bcol = wn * 64 + j * 16;
                wmma::fragment<wmma::matrix_b, 16, 16, 16, __nv_bfloat16, wmma::row_major> bf;
                wmma::load_matrix_sync(bf, Bh + ks * 16 * 136 + bcol, 136);
#pragma unroll
                for (int i = 0; i < 2; i++) {
                    wmma::mma_sync(acc[i][j], ah[i], bf, acc[i][j]);
                    wmma::mma_sync(acc[i][j], al[i], bf, acc[i][j]);
                }
                wmma::load_matrix_sync(bf, Bl + ks * 16 * 136 + bcol, 136);
#pragma unroll
                for (int i = 0; i < 2; i++)
                    wmma::mma_sync(acc[i][j], ah[i], bf, acc[i][j]);
            }
        }
        __syncthreads();
    }

    if (rows == BM) {
#pragma unroll
        for (int i = 0; i < 2; i++)
#pragma unroll
            for (int j = 0; j < 4; j++)
                wmma::store_matrix_sync(
                    g_P + (size_t)(row0 + wm * 32 + i * 16) * DIM + n0 + wn * 64 + j * 16,
                    acc[i][j], DIM, wmma::mem_row_major);
    } else {
#pragma unroll
        for (int half = 0; half < 2; half++) {
            if (wn == half) {
#pragma unroll
                for (int i = 0; i < 2; i++)
#pragma unroll
                    for (int j = 0; j < 4; j++)
                        wmma::store_matrix_sync(stage + (wm * 32 + i * 16) * 72 + j * 16,
                                                acc[i][j], 72, wmma::mem_row_major);
            }
            __syncthreads();
            int row = tid >> 1, h2 = tid & 1;
            if (row < rows) {
                float* dst = g_P + (size_t)(row0 + row) * DIM + n0 + half * 64 + h2 * 32;
#pragma unroll
                for (int j = 0; j < 8; j++)
                    *reinterpret_cast<float4*>(dst + j * 4) =
                        *reinterpret_cast<const float4*>(stage + row * 72 + h2 * 32 + j * 4);
            }
            __syncthreads();
        }
    }
}

// ---------------- combine (verbatim) ------------------------------------------
__global__ void combine_kernel(float* __restrict__ out) {
    int t = blockIdx.x;
    int d = threadIdx.x * 4;
    int pb = t * 2;
    int r0 = g_pos[pb], r1 = g_pos[pb + 1];
    float g0 = g_gate[pb], g1 = g_gate[pb + 1];
    float4 v0 = *reinterpret_cast<const float4*>(g_P + (size_t)r0 * DIM + d);
    float4 v1 = *reinterpret_cast<const float4*>(g_P + (size_t)r1 * DIM + d);
    float4 o;
    o.x = g0 * v0.x + g1 * v1.x;
    o.y = g0 * v0.y + g1 * v1.y;
    o.z = g0 * v0.z + g1 * v1.z;
    o.w = g0 * v0.w + g1 * v1.w;
    *reinterpret_cast<float4*>(out + (size_t)t * DIM + d) = o;
}

// ---------------- launch ------------------------------------------------------
extern "C" void kernel_launch(void* const* d_in, const int* in_sizes, int n_in,
                              void* d_out, int out_size) {
    (void)in_sizes; (void)n_in; (void)out_size;
    const float* x  = (const float*)d_in[0];
    const float* Wr = (const float*)d_in[1];
    const float* W1 = (const float*)d_in[2];
    const float* W2 = (const float*)d_in[3];
    const float* W3 = (const float*)d_in[4];
    float* out = (float*)d_out;

    init_kernel<<<1, 32>>>();
    router_kernel<<<T_TOK / 8, 256>>>(x, Wr);
    scan_kernel<<<1, 1>>>();
    scatter_kernel<<<NP / 256, 256>>>();
    x_split_kernel<<<(T_TOK * DIM) / 1024, 256>>>(x);
    gemm1_wmma<<<dim3(MAXTILES, HID / 64), 256>>>(W1, W3);
    gemm2_wmma<<<dim3(MAXTILES, DIM / 128), 256>>>(W2);
    combine_kernel<<<T_TOK, 256>>>(out);
}

// round 16
// speedup vs baseline: 1.6071x; 1.6071x over previous
#include <cuda_runtime.h>
#include <cuda_bf16.h>
#include <mma.h>
#include <cstdint>

using namespace nvcuda;
typedef unsigned long long ull;

#define T_TOK 4096
#define DIM   1024
#define HID   2048
#define NEXP  8
#define NP    (T_TOK * 2)
#define BM    128
#define MAXTILES (NP / BM + NEXP)   // 72

// ---------------- scratch (112 MB total) -------------------------------------
__device__ int   g_pair[NP];
__device__ int   g_pos[NP];
__device__ float g_gate[NP];
__device__ int   g_expert[NP];
__device__ int   g_counts[NEXP];
__device__ int   g_fill[NEXP];
__device__ int   g_offs[NEXP + 1];
__device__ int   g_tile_e[MAXTILES];
__device__ int   g_tile_r0[MAXTILES];
__device__ int   g_tile_rows[MAXTILES];
__device__ int   g_ntiles;
__device__ float g_P[(size_t)NP * DIM];               // 32 MB
__device__ __nv_bfloat16 g_Hh[(size_t)NP * HID];      // 32 MB
__device__ __nv_bfloat16 g_Hl[(size_t)NP * HID];      // 32 MB
__device__ __nv_bfloat16 g_Xh[(size_t)T_TOK * DIM];   // 8 MB
__device__ __nv_bfloat16 g_Xl[(size_t)T_TOK * DIM];   // 8 MB

// ---------------- truncation split (PRMT prefix) -----------------------------
__device__ __forceinline__ void split4t(float4 v, ull& hp, ull& lp) {
    uint32_t bx = __float_as_uint(v.x), by = __float_as_uint(v.y),
             bz = __float_as_uint(v.z), bw = __float_as_uint(v.w);
    uint32_t h01 = __byte_perm(bx, by, 0x7632);
    uint32_t h23 = __byte_perm(bz, bw, 0x7632);
    float rx = v.x - __uint_as_float(bx & 0xFFFF0000u);
    float ry = v.y - __uint_as_float(by & 0xFFFF0000u);
    float rz = v.z - __uint_as_float(bz & 0xFFFF0000u);
    float rw = v.w - __uint_as_float(bw & 0xFFFF0000u);
    uint32_t l01 = __byte_perm(__float_as_uint(rx), __float_as_uint(ry), 0x7632);
    uint32_t l23 = __byte_perm(__float_as_uint(rz), __float_as_uint(rw), 0x7632);
    hp = (ull)h01 | ((ull)h23 << 32);
    lp = (ull)l01 | ((ull)l23 << 32);
}

// ---------------- routing path ------------------------------------------------
__global__ void init_kernel() {
    int t = threadIdx.x;
    if (t < NEXP) { g_counts[t] = 0; g_fill[t] = 0; }
}

__global__ void router_kernel(const float* __restrict__ x,
                              const float* __restrict__ Wr) {
    int warp = (blockIdx.x * blockDim.x + threadIdx.x) >> 5;
    int lane = threadIdx.x & 31;
    if (warp >= T_TOK) return;
    const float* xr = x + (size_t)warp * DIM;
    float acc[NEXP];
#pragma unroll
    for (int e = 0; e < NEXP; e++) acc[e] = 0.f;
    for (int d = lane; d < DIM; d += 32) {
        float xv = xr[d];
        const float4* w = reinterpret_cast<const float4*>(Wr + (size_t)d * NEXP);
        float4 w0 = w[0], w1 = w[1];
        acc[0] = fmaf(xv, w0.x, acc[0]); acc[1] = fmaf(xv, w0.y, acc[1]);
        acc[2] = fmaf(xv, w0.z, acc[2]); acc[3] = fmaf(xv, w0.w, acc[3]);
        acc[4] = fmaf(xv, w1.x, acc[4]); acc[5] = fmaf(xv, w1.y, acc[5]);
        acc[6] = fmaf(xv, w1.z, acc[6]); acc[7] = fmaf(xv, w1.w, acc[7]);
    }
#pragma unroll
    for (int off = 16; off > 0; off >>= 1)
#pragma unroll
        for (int e = 0; e < NEXP; e++)
            acc[e] += __shfl_down_sync(0xffffffffu, acc[e], off);
    if (lane == 0) {
        int i0 = 0; float m0 = acc[0];
#pragma unroll
        for (int e = 1; e < NEXP; e++)
            if (acc[e] > m0) { m0 = acc[e]; i0 = e; }
        int i1 = -1; float m1 = -3.4e38f;
#pragma unroll
        for (int e = 0; e < NEXP; e++)
            if (e != i0 && acc[e] > m1) { m1 = acc[e]; i1 = e; }
        float g0 = 1.f / (1.f + expf(m1 - m0));
        int p0 = warp * 2, p1 = p0 + 1;
        g_expert[p0] = i0; g_gate[p0] = g0;
        g_expert[p1] = i1; g_gate[p1] = 1.f - g0;
        atomicAdd(&g_counts[i0], 1);
        atomicAdd(&g_counts[i1], 1);
    }
}

__global__ void scan_kernel() {
    int off = 0;
    for (int e = 0; e < NEXP; e++) { g_offs[e] = off; off += g_counts[e]; }
    g_offs[NEXP] = off;
    int nt = 0;
    for (int e = 0; e < NEXP; e++) {
        int c = g_counts[e], base = g_offs[e];
        for (int r = 0; r < c; r += BM) {
            g_tile_e[nt] = e; g_tile_r0[nt] = base + r;
            g_tile_rows[nt] = (c - r < BM) ? (c - r) : BM;
            nt++;
        }
    }
    g_ntiles = nt;
}

__global__ void scatter_kernel() {
    int p = blockIdx.x * blockDim.x + threadIdx.x;
    if (p >= NP) return;
    int e = g_expert[p];
    int row = g_offs[e] + atomicAdd(&g_fill[e], 1);
    g_pair[row] = p;
    g_pos[p] = row;
}

__global__ void x_split_kernel(const float* __restrict__ x) {
    size_t i = ((size_t)blockIdx.x * 256 + threadIdx.x) * 4;
    float4 v = *reinterpret_cast<const float4*>(x + i);
    ull hp, lp; split4t(v, hp, lp);
    *reinterpret_cast<ull*>(&g_Xh[i]) = hp;
    *reinterpret_cast<ull*>(&g_Xl[i]) = lp;
}

// ---------------- GEMM1: h = silu(x@W1)*(x@W3), bf16x3, 2 CTA/SM -------------
#define G1_SMEM 38912

__global__ __launch_bounds__(256, 2)
void gemm1_wmma(const float* __restrict__ W1,
                const float* __restrict__ W3) {
    if ((int)blockIdx.x >= g_ntiles) return;
    __shared__ __align__(16) char sm[G1_SMEM];
    __shared__ int s_tok[128];
    __nv_bfloat16* Ah  = (__nv_bfloat16*)sm;
    __nv_bfloat16* Al  = Ah + 5120;
    __nv_bfloat16* B1h = Ah + 10240;
    __nv_bfloat16* B1l = Ah + 12544;
    __nv_bfloat16* B3h = Ah + 14848;
    __nv_bfloat16* B3l = Ah + 17152;
    float* stage = (float*)sm;

    int e    = g_tile_e[blockIdx.x];
    int row0 = g_tile_r0[blockIdx.x];
    int rows = g_tile_rows[blockIdx.x];
    int n0   = blockIdx.y * 64;
    int tid  = threadIdx.x, wid = tid >> 5;
    int wm = wid & 3, wn = wid >> 2;

    if (tid < 128) s_tok[tid] = (tid < rows) ? (g_pair[row0 + tid] >> 1) : -1;
    __syncthreads();

    const float* W1e = W1 + (size_t)e * DIM * HID;
    const float* W3e = W3 + (size_t)e * DIM * HID;

    wmma::fragment<wmma::accumulator, 16, 16, 16, float> acc1[2][2], acc3[2][2];
#pragma unroll
    for (int i = 0; i < 2; i++)
#pragma unroll
        for (int j = 0; j < 2; j++) {
            wmma::fill_fragment(acc1[i][j], 0.f);
            wmma::fill_fragment(acc3[i][j], 0.f);
        }

    for (int ch = 0; ch < DIM / 32; ch++) {
        int k0 = ch * 32;
#pragma unroll
        for (int p = 0; p < 4; p++) {
            int li = p * 256 + tid;
            int hl = li >> 9, r = (li >> 2) & 127, q = li & 3;
            int tok = s_tok[r];
            uint4 v = make_uint4(0u, 0u, 0u, 0u);
            const __nv_bfloat16* src = hl ? g_Xl : g_Xh;
            if (tok >= 0)
                v = *reinterpret_cast<const uint4*>(src + (size_t)tok * DIM + k0 + q * 8);
            *reinterpret_cast<uint4*>((hl ? Al : Ah) + r * 40 + q * 8) = v;
        }
#pragma unroll
        for (int p = 0; p < 4; p++) {
            int li = p * 256 + tid;
            int t = li >> 9, rr = li & 511, r = rr >> 4, q = rr & 15;
            const float* src = t ? W3e : W1e;
            float4 v = *reinterpret_cast<const float4*>(
                src + (size_t)(k0 + r) * HID + n0 + q * 4);
            ull hp, lp; split4t(v, hp, lp);
            __nv_bfloat16* dh = t ? B3h : B1h;
            __nv_bfloat16* dl = t ? B3l : B1l;
            *reinterpret_cast<ull*>(dh + r * 72 + q * 4) = hp;
            *reinterpret_cast<ull*>(dl + r * 72 + q * 4) = lp;
        }
        __syncthreads();

#pragma unroll
        for (int ks = 0; ks < 2; ks++) {
            wmma::fragment<wmma::matrix_a, 16, 16, 16, __nv_bfloat16, wmma::row_major> ah[2], al[2];
#pragma unroll
            for (int i = 0; i < 2; i++) {
                wmma::load_matrix_sync(ah[i], Ah + (wm * 32 + i * 16) * 40 + ks * 16, 40);
                wmma::load_matrix_sync(al[i], Al + (wm * 32 + i * 16) * 40 + ks * 16, 40);
            }
#pragma unroll
            for (int j = 0; j < 2; j++) {
                int bcol = wn * 32 + j * 16;
                wmma::fragment<wmma::matrix_b, 16, 16, 16, __nv_bfloat16, wmma::row_major> bf;
                wmma::load_matrix_sync(bf, B1h + ks * 16 * 72 + bcol, 72);
#pragma unroll
                for (int i = 0; i < 2; i++) {
                    wmma::mma_sync(acc1[i][j], ah[i], bf, acc1[i][j]);
                    wmma::mma_sync(acc1[i][j], al[i], bf, acc1[i][j]);
                }
                wmma::load_matrix_sync(bf, B1l + ks * 16 * 72 + bcol, 72);
#pragma unroll
                for (int i = 0; i < 2; i++)
                    wmma::mma_sync(acc1[i][j], ah[i], bf, acc1[i][j]);
                wmma::load_matrix_sync(bf, B3h + ks * 16 * 72 + bcol, 72);
#pragma unroll
                for (int i = 0; i < 2; i++) {
                    wmma::mma_sync(acc3[i][j], ah[i], bf, acc3[i][j]);
                    wmma::mma_sync(acc3[i][j], al[i], bf, acc3[i][j]);
                }
                wmma::load_matrix_sync(bf, B3l + ks * 16 * 72 + bcol, 72);
#pragma unroll
                for (int i = 0; i < 2; i++)
                    wmma::mma_sync(acc3[i][j], ah[i], bf, acc3[i][j]);
            }
        }
        __syncthreads();
    }

#pragma unroll
    for (int i = 0; i < 2; i++)
#pragma unroll
        for (int j = 0; j < 2; j++) {
#pragma unroll
            for (int t = 0; t < acc1[i][j].num_elements; t++) {
                float z = acc1[i][j].x[t];
                acc1[i][j].x[t] = z / (1.f + __expf(-z)) * acc3[i][j].x[t];
            }
            wmma::store_matrix_sync(stage + (wm * 32 + i * 16) * 72 + wn * 32 + j * 16,
                                    acc1[i][j], 72, wmma::mem_row_major);
        }
    __syncthreads();

    int row = tid >> 1, half = tid & 1;
    if (row < rows) {
        size_t ob = (size_t)(row0 + row) * HID + n0 + half * 32;
#pragma unroll
        for (int j = 0; j < 8; j++) {
            float4 v = *reinterpret_cast<const float4*>(stage + row * 72 + half * 32 + j * 4);
            ull hp, lp; split4t(v, hp, lp);
            *reinterpret_cast<ull*>(&g_Hh[ob + j * 4]) = hp;
            *reinterpret_cast<ull*>(&g_Hl[ob + j * 4]) = lp;
        }
    }
}

// ---------------- GEMM2: P = h @ W2, 128x128 tiles, 2 CTA/SM ------------------
#define G2_SMEM 37888

__global__ __launch_bounds__(256, 2)
void gemm2_wmma(const float* __restrict__ W2) {
    if ((int)blockIdx.x >= g_ntiles) return;
    __shared__ __align__(16) char sm[G2_SMEM];
    __nv_bfloat16* Ah = (__nv_bfloat16*)sm;
    __nv_bfloat16* Al = Ah + 5120;
    __nv_bfloat16* Bh = Ah + 10240;
    __nv_bfloat16* Bl = Ah + 14592;
    float* stage = (float*)sm;

    int e    = g_tile_e[blockIdx.x];
    int row0 = g_tile_r0[blockIdx.x];
    int rows = g_tile_rows[blockIdx.x];
    int n0   = blockIdx.y * 128;
    int tid  = threadIdx.x, wid = tid >> 5;
    int wm = wid & 3, wn = wid >> 2;

    const float* W2e = W2 + (size_t)e * HID * DIM;

    wmma::fragment<wmma::accumulator, 16, 16, 16, float> acc[2][4];
#pragma unroll
    for (int i = 0; i < 2; i++)
#pragma unroll
        for (int j = 0; j < 4; j++) wmma::fill_fragment(acc[i][j], 0.f);

    for (int ch = 0; ch < HID / 32; ch++) {
        int k0 = ch * 32;
#pragma unroll
        for (int p = 0; p < 2; p++) {
            int li = p * 256 + tid;
            int r = li >> 2, q = li & 3;
            uint4 vh = make_uint4(0u, 0u, 0u, 0u), vl = vh;
            if (r < rows) {
                size_t s = (size_t)(row0 + r) * HID + k0 + q * 8;
                vh = *reinterpret_cast<const uint4*>(&g_Hh[s]);
                vl = *reinterpret_cast<const uint4*>(&g_Hl[s]);
            }
            *reinterpret_cast<uint4*>(Ah + r * 40 + q * 8) = vh;
            *reinterpret_cast<uint4*>(Al + r * 40 + q * 8) = vl;
        }
#pragma unroll
        for (int p = 0; p < 4; p++) {
            int li = p * 256 + tid;
            int r = li >> 5, q = li & 31;
            float4 v = *reinterpret_cast<const float4*>(
                W2e + (size_t)(k0 + r) * DIM + n0 + q * 4);
            ull hp, lp; split4t(v, hp, lp);
            *reinterpret_cast<ull*>(Bh + r * 136 + q * 4) = hp;
            *reinterpret_cast<ull*>(Bl + r * 136 + q * 4) = lp;
        }
        __syncthreads();

#pragma unroll
        for (int ks = 0; ks < 2; ks++) {
            wmma::fragment<wmma::matrix_a, 16, 16, 16, __nv_bfloat16, wmma::row_major> ah[2], al[2];
#pragma unroll
            for (int i = 0; i < 2; i++) {
                wmma::load_matrix_sync(ah[i], Ah + (wm * 32 + i * 16) * 40 + ks * 16, 40);
                wmma::load_matrix_sync(al[i], Al + (wm * 32 + i * 16) * 40 + ks * 16, 40);
            }
#pragma unroll
            for (int j = 0; j < 4; j++) {
                int bcol = wn * 64 + j * 16;
                wmma::fragment<wmma::matrix_b, 16, 16, 16, __nv_bfloat16, wmma::row_major> bf;
                wmma::load_matrix_sync(bf, Bh + ks * 16 * 136 + bcol, 136);
#pragma unroll
                for (int i = 0; i < 2; i++) {
                    wmma::mma_sync(acc[i][j], ah[i], bf, acc[i][j]);
                    wmma::mma_sync(acc[i][j], al[i], bf, acc[i][j]);
                }
                wmma::load_matrix_sync(bf, Bl + ks * 16 * 136 + bcol, 136);
#pragma unroll
                for (int i = 0; i < 2; i++)
                    wmma::mma_sync(acc[i][j], ah[i], bf, acc[i][j]);
            }
        }
        __syncthreads();
    }

    if (rows == BM) {
#pragma unroll
        for (int i = 0; i < 2; i++)
#pragma unroll
            for (int j = 0; j < 4; j++)
                wmma::store_matrix_sync(
                    g_P + (size_t)(row0 + wm * 32 + i * 16) * DIM + n0 + wn * 64 + j * 16,
                    acc[i][j], DIM, wmma::mem_row_major);
    } else {
#pragma unroll
        for (int half = 0; half < 2; half++) {
            if (wn == half) {
#pragma unroll
                for (int i = 0; i < 2; i++)
#pragma unroll
                    for (int j = 0; j < 4; j++)
                        wmma::store_matrix_sync(stage + (wm * 32 + i * 16) * 72 + j * 16,
                                                acc[i][j], 72, wmma::mem_row_major);
            }
            __syncthreads();
            int row = tid >> 1, h2 = tid & 1;
            if (row < rows) {
                float* dst = g_P + (size_t)(row0 + row) * DIM + n0 + half * 64 + h2 * 32;
#pragma unroll
                for (int j = 0; j < 8; j++)
                    *reinterpret_cast<float4*>(dst + j * 4) =
                        *reinterpret_cast<const float4*>(stage + row * 72 + h2 * 32 + j * 4);
            }
            __syncthreads();
        }
    }
}

// ---------------- combine -------------------------------------------------------
__global__ void combine_kernel(float* __restrict__ out) {
    int t = blockIdx.x;
    int d = threadIdx.x * 4;
    int pb = t * 2;
    int r0 = g_pos[pb], r1 = g_pos[pb + 1];
    float g0 = g_gate[pb], g1 = g_gate[pb + 1];
    float4 v0 = *reinterpret_cast<const float4*>(g_P + (size_t)r0 * DIM + d);
    float4 v1 = *reinterpret_cast<const float4*>(g_P + (size_t)r1 * DIM + d);
    float4 o;
    o.x = g0 * v0.x + g1 * v1.x;
    o.y = g0 * v0.y + g1 * v1.y;
    o.z = g0 * v0.z + g1 * v1.z;
    o.w = g0 * v0.w + g1 * v1.w;
    *reinterpret_cast<float4*>(out + (size_t)t * DIM + d) = o;
}

// ---------------- launch ------------------------------------------------------
extern "C" void kernel_launch(void* const* d_in, const int* in_sizes, int n_in,
                              void* d_out, int out_size) {
    (void)in_sizes; (void)n_in; (void)out_size;
    const float* x  = (const float*)d_in[0];
    const float* Wr = (const float*)d_in[1];
    const float* W1 = (const float*)d_in[2];
    const float* W2 = (const float*)d_in[3];
    const float* W3 = (const float*)d_in[4];
    float* out = (float*)d_out;

    init_kernel<<<1, 32>>>();
    router_kernel<<<T_TOK / 8, 256>>>(x, Wr);
    scan_kernel<<<1, 1>>>();
    scatter_kernel<<<NP / 256, 256>>>();
    x_split_kernel<<<(T_TOK * DIM) / 1024, 256>>>(x);
    gemm1_wmma<<<dim3(MAXTILES, HID / 64), 256>>>(W1, W3);
    gemm2_wmma<<<dim3(MAXTILES, DIM / 128), 256>>>(W2);
    combine_kernel<<<T_TOK, 256>>>(out);
}

// round 17
// speedup vs baseline: 1.6593x; 1.0325x over previous
#include <cuda_runtime.h>
#include <cuda_bf16.h>
#include <mma.h>
#include <cstdint>

using namespace nvcuda;
typedef unsigned long long ull;

#define T_TOK 4096
#define DIM   1024
#define HID   2048
#define NEXP  8
#define NP    (T_TOK * 2)
#define BM    128
#define MAXTILES (NP / BM + NEXP)   // 72

// ---------------- scratch (112 MB total) -------------------------------------
__device__ int   g_pair[NP];
__device__ int   g_pos[NP];
__device__ float g_gate[NP];
__device__ int   g_expert[NP];
__device__ int   g_counts[NEXP];
__device__ int   g_fill[NEXP];
__device__ int   g_offs[NEXP + 1];
__device__ int   g_tile_e[MAXTILES];
__device__ int   g_tile_r0[MAXTILES];
__device__ int   g_tile_rows[MAXTILES];
__device__ int   g_ntiles;
__device__ float g_P[(size_t)NP * DIM];               // 32 MB
__device__ __nv_bfloat16 g_Hh[(size_t)NP * HID];      // 32 MB
__device__ __nv_bfloat16 g_Hl[(size_t)NP * HID];      // 32 MB
__device__ __nv_bfloat16 g_Xh[(size_t)T_TOK * DIM];   // 8 MB
__device__ __nv_bfloat16 g_Xl[(size_t)T_TOK * DIM];   // 8 MB

// ---------------- truncation split (PRMT prefix) -----------------------------
__device__ __forceinline__ void split4t(float4 v, ull& hp, ull& lp) {
    uint32_t bx = __float_as_uint(v.x), by = __float_as_uint(v.y),
             bz = __float_as_uint(v.z), bw = __float_as_uint(v.w);
    uint32_t h01 = __byte_perm(bx, by, 0x7632);
    uint32_t h23 = __byte_perm(bz, bw, 0x7632);
    float rx = v.x - __uint_as_float(bx & 0xFFFF0000u);
    float ry = v.y - __uint_as_float(by & 0xFFFF0000u);
    float rz = v.z - __uint_as_float(bz & 0xFFFF0000u);
    float rw = v.w - __uint_as_float(bw & 0xFFFF0000u);
    uint32_t l01 = __byte_perm(__float_as_uint(rx), __float_as_uint(ry), 0x7632);
    uint32_t l23 = __byte_perm(__float_as_uint(rz), __float_as_uint(rw), 0x7632);
    hp = (ull)h01 | ((ull)h23 << 32);
    lp = (ull)l01 | ((ull)l23 << 32);
}

// ---------------- routing path ------------------------------------------------
__global__ void init_kernel() {
    int t = threadIdx.x;
    if (t < NEXP) { g_counts[t] = 0; g_fill[t] = 0; }
}

__global__ void router_kernel(const float* __restrict__ x,
                              const float* __restrict__ Wr) {
    int warp = (blockIdx.x * blockDim.x + threadIdx.x) >> 5;
    int lane = threadIdx.x & 31;
    if (warp >= T_TOK) return;
    const float* xr = x + (size_t)warp * DIM;
    float acc[NEXP];
#pragma unroll
    for (int e = 0; e < NEXP; e++) acc[e] = 0.f;
    for (int d = lane; d < DIM; d += 32) {
        float xv = xr[d];
        const float4* w = reinterpret_cast<const float4*>(Wr + (size_t)d * NEXP);
        float4 w0 = w[0], w1 = w[1];
        acc[0] = fmaf(xv, w0.x, acc[0]); acc[1] = fmaf(xv, w0.y, acc[1]);
        acc[2] = fmaf(xv, w0.z, acc[2]); acc[3] = fmaf(xv, w0.w, acc[3]);
        acc[4] = fmaf(xv, w1.x, acc[4]); acc[5] = fmaf(xv, w1.y, acc[5]);
        acc[6] = fmaf(xv, w1.z, acc[6]); acc[7] = fmaf(xv, w1.w, acc[7]);
    }
#pragma unroll
    for (int off = 16; off > 0; off >>= 1)
#pragma unroll
        for (int e = 0; e < NEXP; e++)
            acc[e] += __shfl_down_sync(0xffffffffu, acc[e], off);
    if (lane == 0) {
        int i0 = 0; float m0 = acc[0];
#pragma unroll
        for (int e = 1; e < NEXP; e++)
            if (acc[e] > m0) { m0 = acc[e]; i0 = e; }
        int i1 = -1; float m1 = -3.4e38f;
#pragma unroll
        for (int e = 0; e < NEXP; e++)
            if (e != i0 && acc[e] > m1) { m1 = acc[e]; i1 = e; }
        float g0 = 1.f / (1.f + expf(m1 - m0));
        int p0 = warp * 2, p1 = p0 + 1;
        g_expert[p0] = i0; g_gate[p0] = g0;
        g_expert[p1] = i1; g_gate[p1] = 1.f - g0;
        atomicAdd(&g_counts[i0], 1);
        atomicAdd(&g_counts[i1], 1);
    }
}

__global__ void scan_kernel() {
    int off = 0;
    for (int e = 0; e < NEXP; e++) { g_offs[e] = off; off += g_counts[e]; }
    g_offs[NEXP] = off;
    int nt = 0;
    for (int e = 0; e < NEXP; e++) {
        int c = g_counts[e], base = g_offs[e];
        for (int r = 0; r < c; r += BM) {
            g_tile_e[nt] = e; g_tile_r0[nt] = base + r;
            g_tile_rows[nt] = (c - r < BM) ? (c - r) : BM;
            nt++;
        }
    }
    g_ntiles = nt;
}

__global__ void scatter_kernel() {
    int p = blockIdx.x * blockDim.x + threadIdx.x;
    if (p >= NP) return;
    int e = g_expert[p];
    int row = g_offs[e] + atomicAdd(&g_fill[e], 1);
    g_pair[row] = p;
    g_pos[p] = row;
}

__global__ void x_split_kernel(const float* __restrict__ x) {
    size_t i = ((size_t)blockIdx.x * 256 + threadIdx.x) * 4;
    float4 v = *reinterpret_cast<const float4*>(x + i);
    ull hp, lp; split4t(v, hp, lp);
    *reinterpret_cast<ull*>(&g_Xh[i]) = hp;
    *reinterpret_cast<ull*>(&g_Xl[i]) = lp;
}

// ---------------- GEMM1: k-chunk 64, dynamic smem, 2 CTA/SM ------------------
// bf16 elems: Ah[128*72]@0 | Al@9216 | B1h[64*72]@18432 | B1l@23040 |
//   B3h@27648 | B3l@32256 -> 36864 elem = 73728 B. Stage [128][72] f32 reuses.
#define G1_SMEM 73728

__global__ __launch_bounds__(256, 2)
void gemm1_wmma(const float* __restrict__ W1,
                const float* __restrict__ W3) {
    if ((int)blockIdx.x >= g_ntiles) return;
    extern __shared__ __align__(16) char sm1[];
    __shared__ int s_tok[128];
    __nv_bfloat16* Ah  = (__nv_bfloat16*)sm1;
    __nv_bfloat16* Al  = Ah + 9216;
    __nv_bfloat16* B1h = Ah + 18432;
    __nv_bfloat16* B1l = Ah + 23040;
    __nv_bfloat16* B3h = Ah + 27648;
    __nv_bfloat16* B3l = Ah + 32256;
    float* stage = (float*)sm1;

    int e    = g_tile_e[blockIdx.x];
    int row0 = g_tile_r0[blockIdx.x];
    int rows = g_tile_rows[blockIdx.x];
    int n0   = blockIdx.y * 64;
    int tid  = threadIdx.x, wid = tid >> 5;
    int wm = wid & 3, wn = wid >> 2;

    if (tid < 128) s_tok[tid] = (tid < rows) ? (g_pair[row0 + tid] >> 1) : -1;
    __syncthreads();

    const float* W1e = W1 + (size_t)e * DIM * HID;
    const float* W3e = W3 + (size_t)e * DIM * HID;

    wmma::fragment<wmma::accumulator, 16, 16, 16, float> acc1[2][2], acc3[2][2];
#pragma unroll
    for (int i = 0; i < 2; i++)
#pragma unroll
        for (int j = 0; j < 2; j++) {
            wmma::fill_fragment(acc1[i][j], 0.f);
            wmma::fill_fragment(acc3[i][j], 0.f);
        }

    for (int ch = 0; ch < DIM / 64; ch++) {
        int k0 = ch * 64;
        // A fill: 128 rows x 64 bf16 x 2 buffers = 2048 uint4 (8/thread)
#pragma unroll
        for (int p = 0; p < 8; p++) {
            int li = p * 256 + tid;
            int hl = li >> 10, rq = li & 1023, r = rq >> 3, q = rq & 7;
            int tok = s_tok[r];
            uint4 v = make_uint4(0u, 0u, 0u, 0u);
            const __nv_bfloat16* src = hl ? g_Xl : g_Xh;
            if (tok >= 0)
                v = *reinterpret_cast<const uint4*>(src + (size_t)tok * DIM + k0 + q * 8);
            *reinterpret_cast<uint4*>((hl ? Al : Ah) + r * 72 + q * 8) = v;
        }
        // B fill: W1,W3 fp32 [64 k-rows][64 n-cols] = 2048 float4 (8/thread)
#pragma unroll
        for (int p = 0; p < 8; p++) {
            int li = p * 256 + tid;
            int t = li >> 10, rq = li & 1023, r = rq >> 4, q = rq & 15;
            const float* src = t ? W3e : W1e;
            float4 v = *reinterpret_cast<const float4*>(
                src + (size_t)(k0 + r) * HID + n0 + q * 4);
            ull hp, lp; split4t(v, hp, lp);
            __nv_bfloat16* dh = t ? B3h : B1h;
            __nv_bfloat16* dl = t ? B3l : B1l;
            *reinterpret_cast<ull*>(dh + r * 72 + q * 4) = hp;
            *reinterpret_cast<ull*>(dl + r * 72 + q * 4) = lp;
        }
        __syncthreads();

#pragma unroll
        for (int ks = 0; ks < 4; ks++) {
            wmma::fragment<wmma::matrix_a, 16, 16, 16, __nv_bfloat16, wmma::row_major> ah[2], al[2];
#pragma unroll
            for (int i = 0; i < 2; i++) {
                wmma::load_matrix_sync(ah[i], Ah + (wm * 32 + i * 16) * 72 + ks * 16, 72);
                wmma::load_matrix_sync(al[i], Al + (wm * 32 + i * 16) * 72 + ks * 16, 72);
            }
#pragma unroll
            for (int j = 0; j < 2; j++) {
                int bcol = wn * 32 + j * 16;
                wmma::fragment<wmma::matrix_b, 16, 16, 16, __nv_bfloat16, wmma::row_major> bf;
                wmma::load_matrix_sync(bf, B1h + ks * 16 * 72 + bcol, 72);
#pragma unroll
                for (int i = 0; i < 2; i++) {
                    wmma::mma_sync(acc1[i][j], ah[i], bf, acc1[i][j]);
                    wmma::mma_sync(acc1[i][j], al[i], bf, acc1[i][j]);
                }
                wmma::load_matrix_sync(bf, B1l + ks * 16 * 72 + bcol, 72);
#pragma unroll
                for (int i = 0; i < 2; i++)
                    wmma::mma_sync(acc1[i][j], ah[i], bf, acc1[i][j]);
                wmma::load_matrix_sync(bf, B3h + ks * 16 * 72 + bcol, 72);
#pragma unroll
                for (int i = 0; i < 2; i++) {
                    wmma::mma_sync(acc3[i][j], ah[i], bf, acc3[i][j]);
                    wmma::mma_sync(acc3[i][j], al[i], bf, acc3[i][j]);
                }
                wmma::load_matrix_sync(bf, B3l + ks * 16 * 72 + bcol, 72);
#pragma unroll
                for (int i = 0; i < 2; i++)
                    wmma::mma_sync(acc3[i][j], ah[i], bf, acc3[i][j]);
            }
        }
        __syncthreads();
    }

#pragma unroll
    for (int i = 0; i < 2; i++)
#pragma unroll
        for (int j = 0; j < 2; j++) {
#pragma unroll
            for (int t = 0; t < acc1[i][j].num_elements; t++) {
                float z = acc1[i][j].x[t];
                acc1[i][j].x[t] = z / (1.f + __expf(-z)) * acc3[i][j].x[t];
            }
            wmma::store_matrix_sync(stage + (wm * 32 + i * 16) * 72 + wn * 32 + j * 16,
                                    acc1[i][j], 72, wmma::mem_row_major);
        }
    __syncthreads();

    int row = tid >> 1, half = tid & 1;
    if (row < rows) {
        size_t ob = (size_t)(row0 + row) * HID + n0 + half * 32;
#pragma unroll
        for (int j = 0; j < 8; j++) {
            float4 v = *reinterpret_cast<const float4*>(stage + row * 72 + half * 32 + j * 4);
            ull hp, lp; split4t(v, hp, lp);
            *reinterpret_cast<ull*>(&g_Hh[ob + j * 4]) = hp;
            *reinterpret_cast<ull*>(&g_Hl[ob + j * 4]) = lp;
        }
    }
}

// ---------------- GEMM2: k-chunk 64, 128x128 tiles, dynamic smem, 2 CTA/SM ---
// bf16 elems: Ah[128*72]@0 | Al@9216 | Bh[64*136]@18432 | Bl@27136
//   -> 35840 elem = 71680 B. Stage [128][72] f32 reuses.
#define G2_SMEM 71680

__global__ __launch_bounds__(256, 2)
void gemm2_wmma(const float* __restrict__ W2) {
    if ((int)blockIdx.x >= g_ntiles) return;
    extern __shared__ __align__(16) char sm2[];
    __nv_bfloat16* Ah = (__nv_bfloat16*)sm2;
    __nv_bfloat16* Al = Ah + 9216;
    __nv_bfloat16* Bh = Ah + 18432;
    __nv_bfloat16* Bl = Ah + 27136;
    float* stage = (float*)sm2;

    int e    = g_tile_e[blockIdx.x];
    int row0 = g_tile_r0[blockIdx.x];
    int rows = g_tile_rows[blockIdx.x];
    int n0   = blockIdx.y * 128;
    int tid  = threadIdx.x, wid = tid >> 5;
    int wm = wid & 3, wn = wid >> 2;

    const float* W2e = W2 + (size_t)e * HID * DIM;

    wmma::fragment<wmma::accumulator, 16, 16, 16, float> acc[2][4];
#pragma unroll
    for (int i = 0; i < 2; i++)
#pragma unroll
        for (int j = 0; j < 4; j++) wmma::fill_fragment(acc[i][j], 0.f);

    for (int ch = 0; ch < HID / 64; ch++) {
        int k0 = ch * 64;
        // A fill: 128 rows x 8 uint4, hi+lo loaded together (4/thread iters)
#pragma unroll
        for (int p = 0; p < 4; p++) {
            int li = p * 256 + tid;
            int r = li >> 3, q = li & 7;
            uint4 vh = make_uint4(0u, 0u, 0u, 0u), vl = vh;
            if (r < rows) {
                size_t s = (size_t)(row0 + r) * HID + k0 + q * 8;
                vh = *reinterpret_cast<const uint4*>(&g_Hh[s]);
                vl = *reinterpret_cast<const uint4*>(&g_Hl[s]);
            }
            *reinterpret_cast<uint4*>(Ah + r * 72 + q * 8) = vh;
            *reinterpret_cast<uint4*>(Al + r * 72 + q * 8) = vl;
        }
        // B fill: 64 k-rows x 128 n-cols fp32 = 2048 float4 (8/thread)
#pragma unroll
        for (int p = 0; p < 8; p++) {
            int li = p * 256 + tid;
            int r = li >> 5, q = li & 31;
            float4 v = *reinterpret_cast<const float4*>(
                W2e + (size_t)(k0 + r) * DIM + n0 + q * 4);
            ull hp, lp; split4t(v, hp, lp);
            *reinterpret_cast<ull*>(Bh + r * 136 + q * 4) = hp;
            *reinterpret_cast<ull*>(Bl + r * 136 + q * 4) = lp;
        }
        __syncthreads();

#pragma unroll
        for (int ks = 0; ks < 4; ks++) {
            wmma::fragment<wmma::matrix_a, 16, 16, 16, __nv_bfloat16, wmma::row_major> ah[2], al[2];
#pragma unroll
            for (int i = 0; i < 2; i++) {
                wmma::load_matrix_sync(ah[i], Ah + (wm * 32 + i * 16) * 72 + ks * 16, 72);
                wmma::load_matrix_sync(al[i], Al + (wm * 32 + i * 16) * 72 + ks * 16, 72);
            }
#pragma unroll
            for (int j = 0; j < 4; j++) {
                int bcol = wn * 64 + j * 16;
                wmma::fragment<wmma::matrix_b, 16, 16, 16, __nv_bfloat16, wmma::row_major> bf;
                wmma::load_matrix_sync(bf, Bh + ks * 16 * 136 + bcol, 136);
#pragma unroll
                for (int i = 0; i < 2; i++) {
                    wmma::mma_sync(acc[i][j], ah[i], bf, acc[i][j]);
                    wmma::mma_sync(acc[i][j], al[i], bf, acc[i][j]);
                }
                wmma::load_matrix_sync(bf, Bl + ks * 16 * 136 + bcol, 136);
#pragma unroll
                for (int i = 0; i < 2; i++)
                    wmma::mma_sync(acc[i][j], ah[i], bf, acc[i][j]);
            }
        }
        __syncthreads();
    }

    if (rows == BM) {
#pragma unroll
        for (int i = 0; i < 2; i++)
#pragma unroll
            for (int j = 0; j < 4; j++)
                wmma::store_matrix_sync(
                    g_P + (size_t)(row0 + wm * 32 + i * 16) * DIM + n0 + wn * 64 + j * 16,
                    acc[i][j], DIM, wmma::mem_row_major);
    } else {
#pragma unroll
        for (int half = 0; half < 2; half++) {
            if (wn == half) {
#pragma unroll
                for (int i = 0; i < 2; i++)
#pragma unroll
                    for (int j = 0; j < 4; j++)
                        wmma::store_matrix_sync(stage + (wm * 32 + i * 16) * 72 + j * 16,
                                                acc[i][j], 72, wmma::mem_row_major);
            }
            __syncthreads();
            int row = tid >> 1, h2 = tid & 1;
            if (row < rows) {
                float* dst = g_P + (size_t)(row0 + row) * DIM + n0 + half * 64 + h2 * 32;
#pragma unroll
                for (int j = 0; j < 8; j++)
                    *reinterpret_cast<float4*>(dst + j * 4) =
                        *reinterpret_cast<const float4*>(stage + row * 72 + h2 * 32 + j * 4);
            }
            __syncthreads();
        }
    }
}

// ---------------- combine -------------------------------------------------------
__global__ void combine_kernel(float* __restrict__ out) {
    int t = blockIdx.x;
    int d = threadIdx.x * 4;
    int pb = t * 2;
    int r0 = g_pos[pb], r1 = g_pos[pb + 1];
    float g0 = g_gate[pb], g1 = g_gate[pb + 1];
    float4 v0 = *reinterpret_cast<const float4*>(g_P + (size_t)r0 * DIM + d);
    float4 v1 = *reinterpret_cast<const float4*>(g_P + (size_t)r1 * DIM + d);
    float4 o;
    o.x = g0 * v0.x + g1 * v1.x;
    o.y = g0 * v0.y + g1 * v1.y;
    o.z = g0 * v0.z + g1 * v1.z;
    o.w = g0 * v0.w + g1 * v1.w;
    *reinterpret_cast<float4*>(out + (size_t)t * DIM + d) = o;
}

// ---------------- launch ------------------------------------------------------
extern "C" void kernel_launch(void* const* d_in, const int* in_sizes, int n_in,
                              void* d_out, int out_size) {
    (void)in_sizes; (void)n_in; (void)out_size;
    const float* x  = (const float*)d_in[0];
    const float* Wr = (const float*)d_in[1];
    const float* W1 = (const float*)d_in[2];
    const float* W2 = (const float*)d_in[3];
    const float* W3 = (const float*)d_in[4];
    float* out = (float*)d_out;

    cudaFuncSetAttribute(gemm1_wmma, cudaFuncAttributeMaxDynamicSharedMemorySize, G1_SMEM);
    cudaFuncSetAttribute(gemm2_wmma, cudaFuncAttributeMaxDynamicSharedMemorySize, G2_SMEM);

    init_kernel<<<1, 32>>>();
    router_kernel<<<T_TOK / 8, 256>>>(x, Wr);
    scan_kernel<<<1, 1>>>();
    scatter_kernel<<<NP / 256, 256>>>();
    x_split_kernel<<<(T_TOK * DIM) / 1024, 256>>>(x);
    gemm1_wmma<<<dim3(MAXTILES, HID / 64), 256, G1_SMEM>>>(W1, W3);
    gemm2_wmma<<<dim3(MAXTILES, DIM / 128), 256, G2_SMEM>>>(W2);
    combine_kernel<<<T_TOK, 256>>>(out);
}